// round 9
// baseline (speedup 1.0000x reference)
#include <cuda_runtime.h>

// VQ-VAE quantization: N=65536 rows x D=64 vs K=1024 codes.
// out = [quantized (N*D) | loss (1) | indices (N)], all f32.
//
// Design: FMA-pipe-bound fp32 path at the packed-f32x2 roofline (~113 us model).
// Frozen until first ncu profile lands; tcgen05 3xTF32 is the next lever but
// needs measured argmin tie margins before it is safe.

#define DIM 64          // feature dim D
#define TK  128         // codebook tile held in smem
#define TPB 256         // threads per block = rows per block

typedef unsigned long long u64;

// Scratch (no device allocations allowed) ------------------------------------
__device__ float g_enorm[4096];     // ||e_k||^2, K <= 4096
__device__ float g_partials[4096];  // per-block squared-error partials

// Packed dual-fp32 ops (sm_103a f32x2 pipe) — exact IEEE fp32 per lane.
__device__ __forceinline__ u64 ffma2(u64 a, u64 b, u64 c) {
    u64 d;
    asm("fma.rn.f32x2 %0, %1, %2, %3;" : "=l"(d) : "l"(a), "l"(b), "l"(c));
    return d;
}
__device__ __forceinline__ u64 fadd2(u64 a, u64 b) {
    u64 d;
    asm("add.rn.f32x2 %0, %1, %2;" : "=l"(d) : "l"(a), "l"(b));
    return d;
}
__device__ __forceinline__ float2 unpack2(u64 a) {
    float2 f;
    asm("mov.b64 {%0, %1}, %2;" : "=f"(f.x), "=f"(f.y) : "l"(a));
    return f;
}

// ---------------------------------------------------------------------------
// 1) Codebook squared norms
// ---------------------------------------------------------------------------
__global__ void enorm_kernel(const float* __restrict__ E, int K) {
    int k = blockIdx.x * blockDim.x + threadIdx.x;
    if (k >= K) return;
    const float4* e = (const float4*)(E + (size_t)k * DIM);
    float s = 0.f;
#pragma unroll
    for (int i = 0; i < DIM / 4; ++i) {
        float4 v = e[i];
        s += v.x * v.x + v.y * v.y + v.z * v.z + v.w * v.w;
    }
    g_enorm[k] = s;
}

// ---------------------------------------------------------------------------
// 2) VQ kernel: one thread = one row, codebook tiled through smem.
//    argmin_j (||e_j||^2 - 2 x.e_j)  ==  argmin_j ||x - e_j||^2  (exact fp32)
//    32 FFMA2/code in 4 independent chains (dep distance = FMA latency 4).
//    Strict < keeps first-min (jax argmin semantics).
// ---------------------------------------------------------------------------
__global__ void __launch_bounds__(TPB, 2)
vq_kernel(const float* __restrict__ X, const float* __restrict__ E,
          float* __restrict__ out, int N, int K) {
    __shared__ u64   s_e[TK * (DIM / 2)];    // 32 KB codebook tile (packed)
    __shared__ float s_en[TK];
    __shared__ float s_red[TPB];

    const int row = blockIdx.x * TPB + threadIdx.x;
    const bool live = (row < N);

    // row into 32 packed-pair registers
    u64 xp[DIM / 2];
    if (live) {
        const ulonglong2* xr = (const ulonglong2*)(X + (size_t)row * DIM);
#pragma unroll
        for (int i = 0; i < DIM / 4; ++i) {
            ulonglong2 v = xr[i];
            xp[2 * i]     = v.x;
            xp[2 * i + 1] = v.y;
        }
    } else {
#pragma unroll
        for (int i = 0; i < DIM / 2; ++i) xp[i] = 0ull;
    }

    float minv = 3.4e38f;
    int   mini = 0;

    for (int t = 0; t < K; t += TK) {
        __syncthreads();
        // cooperative coalesced tile load (8 fixed strided LDG.128 / thread)
        const ulonglong2* Eg = (const ulonglong2*)(E + (size_t)t * DIM);
        ulonglong2* Es = (ulonglong2*)s_e;
#pragma unroll 8
        for (int i = threadIdx.x; i < TK * (DIM / 4); i += TPB) Es[i] = Eg[i];
        if (threadIdx.x < TK) s_en[threadIdx.x] = g_enorm[t + threadIdx.x];
        __syncthreads();

#pragma unroll 2
        for (int j = 0; j < TK; ++j) {
            const ulonglong2* e = (const ulonglong2*)&s_e[j * (DIM / 2)];
            u64 a0 = 0ull, a1 = 0ull, a2 = 0ull, a3 = 0ull;  // {0f,0f}
#pragma unroll
            for (int i = 0; i < DIM / 8; ++i) {
                ulonglong2 v0 = e[2 * i];
                ulonglong2 v1 = e[2 * i + 1];
                a0 = ffma2(xp[4 * i + 0], v0.x, a0);
                a1 = ffma2(xp[4 * i + 1], v0.y, a1);
                a2 = ffma2(xp[4 * i + 2], v1.x, a2);
                a3 = ffma2(xp[4 * i + 3], v1.y, a3);
            }
            // packed reduction: 3 f32x2 adds, 1 unpack, 1 add, 1 fma
            u64 s = fadd2(fadd2(a0, a1), fadd2(a2, a3));
            float2 f = unpack2(s);
            float d = fmaf(-2.f, f.x + f.y, s_en[j]);
            if (d < minv) { minv = d; mini = t + j; }   // first min wins
        }
    }

    // gather winning code, write quantized row, accumulate squared error
    float sq = 0.f;
    if (live) {
        const float4* eq = (const float4*)(E + (size_t)mini * DIM);
        const float4* xf = (const float4*)(X + (size_t)row * DIM);
        float4* orow = (float4*)(out + (size_t)row * DIM);
#pragma unroll
        for (int i = 0; i < DIM / 4; ++i) {
            float4 v = eq[i];
            float4 u = xf[i];
            float dx = v.x - u.x, dy = v.y - u.y,
                  dz = v.z - u.z, dw = v.w - u.w;
            sq += dx * dx + dy * dy + dz * dz + dw * dw;
            orow[i] = v;
        }
        // indices region: after quantized [N*D] and loss [1]
        out[(size_t)N * DIM + 1 + row] = (float)mini;
    }

    // deterministic block reduction of squared error
    s_red[threadIdx.x] = sq;
    __syncthreads();
#pragma unroll
    for (int o = TPB / 2; o > 0; o >>= 1) {
        if (threadIdx.x < o) s_red[threadIdx.x] += s_red[threadIdx.x + o];
        __syncthreads();
    }
    if (threadIdx.x == 0) g_partials[blockIdx.x] = s_red[0];
}

// ---------------------------------------------------------------------------
// 3) Final loss reduce: loss = 1.25 * mean((q - x)^2)
// ---------------------------------------------------------------------------
__global__ void loss_kernel(float* __restrict__ out, int nPart, float inv_elems,
                            size_t loss_off) {
    __shared__ float s[TPB];
    float v = 0.f;
    for (int i = threadIdx.x; i < nPart; i += TPB) v += g_partials[i];
    s[threadIdx.x] = v;
    __syncthreads();
#pragma unroll
    for (int o = TPB / 2; o > 0; o >>= 1) {
        if (threadIdx.x < o) s[threadIdx.x] += s[threadIdx.x + o];
        __syncthreads();
    }
    if (threadIdx.x == 0) out[loss_off] = 1.25f * s[0] * inv_elems;
}

// ---------------------------------------------------------------------------
extern "C" void kernel_launch(void* const* d_in, const int* in_sizes, int n_in,
                              void* d_out, int out_size) {
    const float* X = (const float*)d_in[0];   // inputs   [N, D] flattened
    const float* E = (const float*)d_in[1];   // codebook [K, D]
    float* out = (float*)d_out;

    const int N = in_sizes[0] / DIM;          // 65536
    const int K = in_sizes[1] / DIM;          // 1024

    const int nBlocks = (N + TPB - 1) / TPB;
    enorm_kernel<<<(K + 255) / 256, 256>>>(E, K);
    vq_kernel<<<nBlocks, TPB>>>(X, E, out, N, K);
    loss_kernel<<<1, TPB>>>(out, nBlocks, 1.0f / (float)in_sizes[0],
                            (size_t)N * DIM);
}

// round 15
// speedup vs baseline: 1.6958x; 1.6958x over previous
#include <cuda_runtime.h>
#include <cuda_bf16.h>
#include <cstdint>

// VQ-VAE quantization: N=65536 x D=64 vs K=1024 codes.
// out = [quantized (N*D) | loss (1) | indices (N)], f32.
// Tensor path: bf16x3-split (6-product) GEMM on baseline mma.sync (sm_80 PTX,
// compiles for the family target sm_103 — tcgen05 is 'a'-gated and rejected
// by this harness's PTX stage).

#define DIM   64
#define NMAX  65536
#define KMAX  1024
#define TPB   256         // 8 warps
#define RPC   128         // rows per CTA
#define TILE  64          // codes per smem tile
#define BPAD  72          // bf16 elems per padded code row (144 B)

typedef unsigned long long u64;

// ---- device scratch (no allocations allowed) -------------------------------
__device__ __align__(16) __nv_bfloat16 g_xs0[NMAX * DIM];
__device__ __align__(16) __nv_bfloat16 g_xs1[NMAX * DIM];
__device__ __align__(16) __nv_bfloat16 g_xs2[NMAX * DIM];
__device__ __align__(16) __nv_bfloat16 g_es0[KMAX * DIM];
__device__ __align__(16) __nv_bfloat16 g_es1[KMAX * DIM];
__device__ __align__(16) __nv_bfloat16 g_es2[KMAX * DIM];
__device__ float g_enorm[KMAX];
__device__ float g_partials[NMAX / RPC];

// mma.sync m16n8k16 bf16 -> f32 accumulate (baseline PTX, sm_80+)
__device__ __forceinline__ void mma16816(float& c0, float& c1, float& c2, float& c3,
                                         uint32_t a0, uint32_t a1, uint32_t a2, uint32_t a3,
                                         uint32_t b0, uint32_t b1) {
    asm volatile(
        "mma.sync.aligned.m16n8k16.row.col.f32.bf16.bf16.f32 "
        "{%0,%1,%2,%3}, {%4,%5,%6,%7}, {%8,%9}, {%0,%1,%2,%3};"
        : "+f"(c0), "+f"(c1), "+f"(c2), "+f"(c3)
        : "r"(a0), "r"(a1), "r"(a2), "r"(a3), "r"(b0), "r"(b1));
}

// ---------------------------------------------------------------------------
// bf16x3 splits (residual <= 2^-27 |x|)
// ---------------------------------------------------------------------------
__global__ void split_x_kernel(const float* __restrict__ X, int n) {
    int i = blockIdx.x * blockDim.x + threadIdx.x;
    if (i >= n) return;
    float f = X[i];
    __nv_bfloat16 b0 = __float2bfloat16_rn(f);
    float r1 = f - __bfloat162float(b0);
    __nv_bfloat16 b1 = __float2bfloat16_rn(r1);
    float r2 = r1 - __bfloat162float(b1);
    g_xs0[i] = b0; g_xs1[i] = b1; g_xs2[i] = __float2bfloat16_rn(r2);
}
__global__ void split_e_kernel(const float* __restrict__ E, int n) {
    int i = blockIdx.x * blockDim.x + threadIdx.x;
    if (i >= n) return;
    float f = E[i];
    __nv_bfloat16 b0 = __float2bfloat16_rn(f);
    float r1 = f - __bfloat162float(b0);
    __nv_bfloat16 b1 = __float2bfloat16_rn(r1);
    float r2 = r1 - __bfloat162float(b1);
    g_es0[i] = b0; g_es1[i] = b1; g_es2[i] = __float2bfloat16_rn(r2);
}
__global__ void enorm_kernel(const float* __restrict__ E, int K) {
    int k = blockIdx.x * blockDim.x + threadIdx.x;
    if (k >= K) return;
    const float4* e = (const float4*)(E + (size_t)k * DIM);
    float s = 0.f;
#pragma unroll
    for (int i = 0; i < DIM / 4; ++i) {
        float4 v = e[i];
        s += v.x * v.x + v.y * v.y + v.z * v.z + v.w * v.w;
    }
    g_enorm[k] = s;
}

// ---------------------------------------------------------------------------
// Main: warp-level bf16 MMA + argmin. CTA=256 thr (8 warps), 128 rows.
// Warp w owns rows 16w..16w+15; A frags in regs; B tiles via smem (padded).
// argmin(||e||^2 - 2 x.e) == argmin ||x-e||^2; first-min semantics kept via
// ascending scan + index tiebreak in the quad butterfly.
// ---------------------------------------------------------------------------
__global__ void __launch_bounds__(TPB, 2)
vq_mma_kernel(const float* __restrict__ X, const float* __restrict__ E,
              float* __restrict__ out, int N, int K) {
    __shared__ __align__(16) __nv_bfloat16 s_b[3][TILE][BPAD];  // ~27.6 KB
    __shared__ float s_en[TILE];
    __shared__ int   s_idx[RPC];
    __shared__ float s_red[TPB];

    const int tid = threadIdx.x;
    const int wid = tid >> 5, lane = tid & 31;
    const int q = lane & 3, g = lane >> 2;            // quad id, group id
    const int rowA = blockIdx.x * RPC + wid * 16 + g; // this thread's rows
    const int rowB = rowA + 8;

    // ---- A fragments: [comp][kstep][a0..a3], one-time global loads --------
    uint32_t af[3][4][4];
    {
        const __nv_bfloat16* srcs[3] = {g_xs0, g_xs1, g_xs2};
#pragma unroll
        for (int c = 0; c < 3; ++c) {
            const __nv_bfloat16* pA = srcs[c] + (size_t)rowA * DIM;
            const __nv_bfloat16* pB = srcs[c] + (size_t)rowB * DIM;
#pragma unroll
            for (int k = 0; k < 4; ++k) {
                int base = k * 16 + 2 * q;
                af[c][k][0] = *(const uint32_t*)(pA + base);
                af[c][k][1] = *(const uint32_t*)(pB + base);
                af[c][k][2] = *(const uint32_t*)(pA + base + 8);
                af[c][k][3] = *(const uint32_t*)(pB + base + 8);
            }
        }
    }

    float minvA = 3.4e38f, minvB = 3.4e38f;
    int   minA = 0, minB = 0;
    const int ntiles = K / TILE;   // 16

    for (int t = 0; t < ntiles; ++t) {
        __syncthreads();           // previous tile's LDS done
        // ---- cooperative B-tile load: 3 comps x 64 codes x 128 B ----------
        {
            const __nv_bfloat16* srcs[3] = {g_es0, g_es1, g_es2};
            for (int i = tid; i < 3 * TILE * 8; i += TPB) {   // uint4 chunks
                int c = i >> 9, rem = i & 511, code = rem >> 3, ch = rem & 7;
                const uint4* src =
                    (const uint4*)(srcs[c] + (size_t)(t * TILE + code) * DIM) + ch;
                *(uint4*)(&s_b[c][code][ch * 8]) = *src;
            }
            if (tid < TILE) s_en[tid] = g_enorm[t * TILE + tid];
        }
        __syncthreads();

        // ---- 8 n-frags of 8 codes; 6 comp-pairs x 4 k-steps each ----------
        const int PA[6] = {0, 0, 1, 1, 0, 2};
        const int PB[6] = {0, 1, 0, 1, 2, 0};
#pragma unroll
        for (int nf = 0; nf < 8; ++nf) {
            float c0 = 0.f, c1 = 0.f, c2 = 0.f, c3 = 0.f;
            const int code = nf * 8 + g;
#pragma unroll
            for (int p = 0; p < 6; ++p) {
                const __nv_bfloat16* bp = &s_b[PB[p]][code][0];
#pragma unroll
                for (int k = 0; k < 4; ++k) {
                    uint32_t b0 = *(const uint32_t*)(bp + k * 16 + 2 * q);
                    uint32_t b1 = *(const uint32_t*)(bp + k * 16 + 2 * q + 8);
                    mma16816(c0, c1, c2, c3,
                             af[PA[p]][k][0], af[PA[p]][k][1],
                             af[PA[p]][k][2], af[PA[p]][k][3], b0, b1);
                }
            }
            // C layout: c0/c1 -> rowA cols 2q,2q+1 ; c2/c3 -> rowB same cols
            const int col = t * TILE + nf * 8 + 2 * q;
            float d;
            d = fmaf(-2.f, c0, s_en[nf * 8 + 2 * q]);
            if (d < minvA) { minvA = d; minA = col; }
            d = fmaf(-2.f, c1, s_en[nf * 8 + 2 * q + 1]);
            if (d < minvA) { minvA = d; minA = col + 1; }
            d = fmaf(-2.f, c2, s_en[nf * 8 + 2 * q]);
            if (d < minvB) { minvB = d; minB = col; }
            d = fmaf(-2.f, c3, s_en[nf * 8 + 2 * q + 1]);
            if (d < minvB) { minvB = d; minB = col + 1; }
        }
    }

    // ---- quad butterfly with index tiebreak (first-min == jnp.argmin) -----
#pragma unroll
    for (int dlt = 1; dlt < 4; dlt <<= 1) {
        float ov; int oi;
        ov = __shfl_xor_sync(0xffffffffu, minvA, dlt);
        oi = __shfl_xor_sync(0xffffffffu, minA, dlt);
        if (ov < minvA || (ov == minvA && oi < minA)) { minvA = ov; minA = oi; }
        ov = __shfl_xor_sync(0xffffffffu, minvB, dlt);
        oi = __shfl_xor_sync(0xffffffffu, minB, dlt);
        if (ov < minvB || (ov == minvB && oi < minB)) { minvB = ov; minB = oi; }
    }
    if (q == 0) {
        s_idx[wid * 16 + g]     = minA;
        s_idx[wid * 16 + g + 8] = minB;
    }
    __syncthreads();

    // ---- epilogue: threads 0..127 own rows; outputs from original f32 -----
    float sq = 0.f;
    if (tid < RPC) {
        const int row = blockIdx.x * RPC + tid;
        const int mini = s_idx[tid];
        const float4* eq = (const float4*)(E + (size_t)mini * DIM);
        const float4* xf = (const float4*)(X + (size_t)row * DIM);
        float4* orow = (float4*)(out + (size_t)row * DIM);
#pragma unroll
        for (int i = 0; i < DIM / 4; ++i) {
            float4 v = eq[i], u = xf[i];
            float dx = v.x - u.x, dy = v.y - u.y,
                  dz = v.z - u.z, dw = v.w - u.w;
            sq += dx * dx + dy * dy + dz * dz + dw * dw;
            orow[i] = v;
        }
        out[(size_t)N * DIM + 1 + row] = (float)mini;
    }
    s_red[tid] = sq;
    __syncthreads();
#pragma unroll
    for (int o = TPB / 2; o > 0; o >>= 1) {
        if (tid < o) s_red[tid] += s_red[tid + o];
        __syncthreads();
    }
    if (tid == 0) g_partials[blockIdx.x] = s_red[0];
}

// ---------------------------------------------------------------------------
__global__ void loss_kernel(float* __restrict__ out, int nPart, float inv_elems,
                            size_t loss_off) {
    __shared__ float s[256];
    float v = 0.f;
    for (int i = threadIdx.x; i < nPart; i += 256) v += g_partials[i];
    s[threadIdx.x] = v;
    __syncthreads();
#pragma unroll
    for (int o = 128; o > 0; o >>= 1) {
        if (threadIdx.x < o) s[threadIdx.x] += s[threadIdx.x + o];
        __syncthreads();
    }
    if (threadIdx.x == 0) out[loss_off] = 1.25f * s[0] * inv_elems;
}

// ---------------------------------------------------------------------------
extern "C" void kernel_launch(void* const* d_in, const int* in_sizes, int n_in,
                              void* d_out, int out_size) {
    const float* X = (const float*)d_in[0];
    const float* E = (const float*)d_in[1];
    float* out = (float*)d_out;

    const int N = in_sizes[0] / DIM;   // 65536
    const int K = in_sizes[1] / DIM;   // 1024
    const int nBlocks = N / RPC;       // 512

    split_x_kernel<<<(in_sizes[0] + 255) / 256, 256>>>(X, in_sizes[0]);
    split_e_kernel<<<(in_sizes[1] + 255) / 256, 256>>>(E, in_sizes[1]);
    enorm_kernel<<<(K + 255) / 256, 256>>>(E, K);
    vq_mma_kernel<<<nBlocks, TPB>>>(X, E, out, N, K);
    loss_kernel<<<1, 256>>>(out, nBlocks, 1.0f / (float)in_sizes[0],
                            (size_t)N * DIM);
}